// round 9
// baseline (speedup 1.0000x reference)
#include <cuda_runtime.h>
#include <math.h>

// Problem constants
#define B_  32
#define T_  2048
#define D_  512
#define H_  512
#define G_  2048          // 4*H
#define BT_ 65536         // B*T
#define NCTA_REC 128

// ---------------------------------------------------------------------------
// Scratch (device globals per harness rules: no cudaMalloc anywhere)
// ---------------------------------------------------------------------------
__device__ float g_xg[65536ULL * 2048ULL];   // (T, B, G) layout: xg[t][b][g]
__device__ float g_h[2][B_ * H_];            // double-buffered hidden state
__device__ unsigned g_flags[NCTA_REC];       // monotone per-CTA arrive flags
__device__ unsigned g_go;                    // monotone master release flag

__device__ __forceinline__ unsigned ld_acq_u32(const unsigned* p) {
    unsigned v;
    asm volatile("ld.acquire.gpu.global.u32 %0, [%1];" : "=r"(v) : "l"(p));
    return v;
}
__device__ __forceinline__ void st_rel_u32(unsigned* p, unsigned v) {
    asm volatile("st.release.gpu.global.u32 [%0], %1;" :: "l"(p), "r"(v));
}

// ---------------------------------------------------------------------------
// Kernel A: xg[t][b][g] = sum_d x[b][t][d] * W[d][g] + bias[g]
// fp32 SIMT GEMM, 128x128 tile, BK=8, 256 threads, 8x8 per-thread tile.
// NEW (this round): register prefetch of the next BK tile — global loads for
// iteration i+1 issue right after the first __syncthreads of iteration i and
// are consumed at its end, hiding LDG latency under the 512-FMA compute block.
// Same k-order / FMA order as round 3 -> bit-identical xg.
// ---------------------------------------------------------------------------
__global__ __launch_bounds__(256) void xg_gemm(const float* __restrict__ x,
                                               const float* __restrict__ W,
                                               const float* __restrict__ bias) {
    __shared__ float As[8][128];   // As[k][m]
    __shared__ float Ws[8][128];   // Ws[k][n]

    const int rowBase = blockIdx.y * 128;
    const int colBase = blockIdx.x * 128;
    const int tid = threadIdx.x;

    const int arow = tid >> 1;
    const int ak4  = (tid & 1) * 4;
    const int wrow = tid >> 5;
    const int wc4  = (tid & 31) * 4;
    const int tm   = (tid >> 4) * 8;
    const int tn   = (tid & 15) * 8;

    float acc[8][8];
#pragma unroll
    for (int i = 0; i < 8; i++)
#pragma unroll
        for (int j = 0; j < 8; j++) acc[i][j] = 0.f;

    const float* xp = &x[(size_t)(rowBase + arow) * 512 + ak4];
    const float* wp = &W[(size_t)wrow * 2048 + colBase + wc4];

    // Prefetch tile 0
    float4 av = *(const float4*)&xp[0];
    float4 wv = *(const float4*)&wp[0];

    for (int k0 = 0; k0 < 512; k0 += 8) {
        // Store the prefetched tile into SMEM
        As[ak4 + 0][arow] = av.x;
        As[ak4 + 1][arow] = av.y;
        As[ak4 + 2][arow] = av.z;
        As[ak4 + 3][arow] = av.w;
        *(float4*)&Ws[wrow][wc4] = wv;
        __syncthreads();

        // Prefetch next tile into registers (hidden under the compute below)
        if (k0 + 8 < 512) {
            av = *(const float4*)&xp[k0 + 8];
            wv = *(const float4*)&wp[(size_t)(k0 + 8) * 2048];
        }

#pragma unroll
        for (int kk = 0; kk < 8; kk++) {
            float a[8], w[8];
            *(float4*)&a[0] = *(const float4*)&As[kk][tm];
            *(float4*)&a[4] = *(const float4*)&As[kk][tm + 4];
            *(float4*)&w[0] = *(const float4*)&Ws[kk][tn];
            *(float4*)&w[4] = *(const float4*)&Ws[kk][tn + 4];
#pragma unroll
            for (int i = 0; i < 8; i++)
#pragma unroll
                for (int j = 0; j < 8; j++)
                    acc[i][j] = fmaf(a[i], w[j], acc[i][j]);
        }
        __syncthreads();
    }

    float bb[8];
    *(float4*)&bb[0] = *(const float4*)&bias[colBase + tn];
    *(float4*)&bb[4] = *(const float4*)&bias[colBase + tn + 4];

#pragma unroll
    for (int i = 0; i < 8; i++) {
        int r = rowBase + tm + i;
        int t = r & (T_ - 1);
        int b = r >> 11;
        float* dst = &g_xg[((size_t)t * B_ + b) * G_ + colBase + tn];
        float4 v0 = make_float4(acc[i][0] + bb[0], acc[i][1] + bb[1],
                                acc[i][2] + bb[2], acc[i][3] + bb[3]);
        float4 v1 = make_float4(acc[i][4] + bb[4], acc[i][5] + bb[5],
                                acc[i][6] + bb[6], acc[i][7] + bb[7]);
        *(float4*)&dst[0] = v0;
        *(float4*)&dst[4] = v1;
    }
}

// ---------------------------------------------------------------------------
// Kernel B: persistent recurrence — EXACT round-8 version (winning kernel).
// CTA j owns h-columns [4j, 4j+4) -> 16 gate columns (gl = gtype*4 + hcl).
// Dot-phase: warp=batch-quad, quarter-warp=gate-type, lane=K/8 segment;
// 4x4 output tile per thread over K=64; k-rotation kills LDS conflicts.
// Barrier: round-3 master-aggregator.
// ---------------------------------------------------------------------------
#define WSTRIDE  516
#define SM_W     0
#define SM_HS    (16 * WSTRIDE)               // 8256
#define SM_PART  (SM_HS + 32 * WSTRIDE)       // 24768
#define PART_BQ  20                           // kq stride (words)
#define PART_BB  164                          // b stride (words)
#define SM_CS    (SM_PART + 32 * PART_BB)     // 30016
#define SMEM_FLOATS (SM_CS + 128)             // 30144 floats = 120.6 KB

#define FMA4(ACC, H, Wv) \
    ACC = fmaf((H).x, (Wv).x, fmaf((H).y, (Wv).y, \
          fmaf((H).z, (Wv).z, fmaf((H).w, (Wv).w, ACC))))

__global__ __launch_bounds__(256) void lstm_rec(const float* __restrict__ W,
                                                const float* __restrict__ h0,
                                                const float* __restrict__ c0,
                                                float* __restrict__ out) {
    extern __shared__ float sm[];
    float* Ws16 = sm + SM_W;         // Ws16[gl*WSTRIDE + k]
    float* hs   = sm + SM_HS;        // hs[b*WSTRIDE + k]
    float* part = sm + SM_PART;      // part[b*164 + kq*20 + gl]
    float* cs   = sm + SM_CS;        // cs[hcl*32 + b]

    const int tid = threadIdx.x;
    const int j   = blockIdx.x;      // 0..127
    const int jb  = j * 4;

    for (int e = tid; e < 8192; e += 256) {
        int k  = e >> 4;
        int gl = e & 15;
        int gcol = (gl >> 2) * 512 + jb + (gl & 3);
        Ws16[gl * WSTRIDE + k] = W[(size_t)(512 + k) * 2048 + gcol];
    }
    if (tid < 128) {
        int b = tid >> 2, hcl = tid & 3;
        cs[hcl * 32 + b] = c0[b * 512 + jb + hcl];
    }
    __shared__ unsigned s_fb, s_gb;
    if (tid == 0) {
        s_fb = *(volatile unsigned*)&g_flags[j];
        s_gb = *(volatile unsigned*)&g_go;
    }
    __syncthreads();
    const unsigned fbase = s_fb;
    const unsigned gbase = s_gb;

    const int bq = tid >> 5;         // warp: batch quad
    const int gq = (tid >> 3) & 3;   // quarter: gate type
    const int kq = tid & 7;          // lane-in-quarter: K segment
    const float* hb = &hs[(bq * 4) * WSTRIDE];
    const float* wb = &Ws16[(gq * 4) * WSTRIDE];
    const int kb = kq * 64;
    float* pst = &part[kq * PART_BQ + gq * 4];

    const int cb  = tid >> 2;        // 0..31 (valid when tid<128)
    const int hcl = tid & 3;

    for (int t = 0; t < T_; t++) {
        float gx0 = 0.f, gx1 = 0.f, gx2 = 0.f, gx3 = 0.f;
        if (tid < 128) {
            const float* xp = &g_xg[((size_t)t * B_ + cb) * G_ + jb + hcl];
            gx0 = xp[0];
            gx1 = xp[512];
            gx2 = xp[1024];
            gx3 = xp[1536];
        }

        const float* hsrc = (t == 0) ? h0 : g_h[t & 1];
        for (int i4 = tid; i4 < 4096; i4 += 256) {
            int bb2 = i4 >> 7, k4 = (i4 & 127) * 4;
            *(float4*)&hs[bb2 * WSTRIDE + k4] = *(const float4*)&hsrc[bb2 * 512 + k4];
        }
        __syncthreads();

        float a0x = 0.f, a0y = 0.f, a0z = 0.f, a0w = 0.f;
        float a1x = 0.f, a1y = 0.f, a1z = 0.f, a1w = 0.f;
        float a2x = 0.f, a2y = 0.f, a2z = 0.f, a2w = 0.f;
        float a3x = 0.f, a3y = 0.f, a3z = 0.f, a3w = 0.f;
#pragma unroll 4
        for (int i = 0; i < 16; i++) {
            int ko = kb + (((i + kq) & 15) << 2);
            float4 h0 = *(const float4*)&hb[0 * WSTRIDE + ko];
            float4 h1 = *(const float4*)&hb[1 * WSTRIDE + ko];
            float4 h2 = *(const float4*)&hb[2 * WSTRIDE + ko];
            float4 h3 = *(const float4*)&hb[3 * WSTRIDE + ko];
            float4 w0 = *(const float4*)&wb[0 * WSTRIDE + ko];
            float4 w1 = *(const float4*)&wb[1 * WSTRIDE + ko];
            float4 w2 = *(const float4*)&wb[2 * WSTRIDE + ko];
            float4 w3 = *(const float4*)&wb[3 * WSTRIDE + ko];
            FMA4(a0x, h0, w0); FMA4(a0y, h0, w1); FMA4(a0z, h0, w2); FMA4(a0w, h0, w3);
            FMA4(a1x, h1, w0); FMA4(a1y, h1, w1); FMA4(a1z, h1, w2); FMA4(a1w, h1, w3);
            FMA4(a2x, h2, w0); FMA4(a2y, h2, w1); FMA4(a2z, h2, w2); FMA4(a2w, h2, w3);
            FMA4(a3x, h3, w0); FMA4(a3y, h3, w1); FMA4(a3z, h3, w2); FMA4(a3w, h3, w3);
        }
        *(float4*)&pst[(4 * bq + 0) * PART_BB] = make_float4(a0x, a0y, a0z, a0w);
        *(float4*)&pst[(4 * bq + 1) * PART_BB] = make_float4(a1x, a1y, a1z, a1w);
        *(float4*)&pst[(4 * bq + 2) * PART_BB] = make_float4(a2x, a2y, a2z, a2w);
        *(float4*)&pst[(4 * bq + 3) * PART_BB] = make_float4(a3x, a3y, a3z, a3w);
        __syncthreads();

        if (tid < 128) {
            float s0 = gx0, s1 = gx1, s2 = gx2, s3 = gx3;
            const float* pb = &part[cb * PART_BB + hcl];
#pragma unroll
            for (int q = 0; q < 8; q++) {
                s0 += pb[q * PART_BQ + 0];
                s1 += pb[q * PART_BQ + 4];
                s2 += pb[q * PART_BQ + 8];
                s3 += pb[q * PART_BQ + 12];
            }
            float iv = 1.f / (1.f + expf(-s0));
            float fv = 1.f / (1.f + expf(-s1));
            float gv = tanhf(s2);
            float ov = 1.f / (1.f + expf(-s3));
            float c = fv * cs[hcl * 32 + cb] + iv * gv;
            cs[hcl * 32 + cb] = c;
            float h = ov * tanhf(c);
            g_h[(t + 1) & 1][cb * 512 + jb + hcl] = h;       // critical path
            out[((size_t)cb * T_ + t) * H_ + jb + hcl] = h;  // outputs[b][t][hc]
            if (t == T_ - 1) {
                out[(size_t)BT_ * H_ + cb * 512 + jb + hcl]           = h;  // h_T
                out[(size_t)BT_ * H_ + B_ * H_ + cb * 512 + jb + hcl] = c;  // c_T
            }
        }
        __syncthreads();

        if (t < T_ - 1) {
            const unsigned step = (unsigned)t + 1u;
            if (tid == 0) st_rel_u32(&g_flags[j], fbase + step);  // arrive
            if (j == 0) {
                if (tid < NCTA_REC) {
                    while ((int)(ld_acq_u32(&g_flags[tid]) - (fbase + step)) < 0) { }
                }
                __syncthreads();
                if (tid == 0) st_rel_u32(&g_go, gbase + step);
            } else {
                if (tid == 0) {
                    while ((int)(ld_acq_u32(&g_go) - (gbase + step)) < 0) { }
                }
                __syncthreads();
            }
        }
    }
}

// ---------------------------------------------------------------------------
// Launcher
// ---------------------------------------------------------------------------
extern "C" void kernel_launch(void* const* d_in, const int* in_sizes, int n_in,
                              void* d_out, int out_size) {
    const float* x    = (const float*)d_in[0];   // (B, T, D)
    const float* W    = (const float*)d_in[1];   // (D+H, 4H)
    const float* bias = (const float*)d_in[2];   // (4H,)
    const float* h0   = (const float*)d_in[3];   // (B, H)
    const float* c0   = (const float*)d_in[4];   // (B, H)
    float* out = (float*)d_out;                  // outputs | h_T | c_T

    dim3 grid(G_ / 128, BT_ / 128);
    xg_gemm<<<grid, 256>>>(x, W, bias);

    size_t smem = SMEM_FLOATS * sizeof(float);
    cudaFuncSetAttribute(lstm_rec, cudaFuncAttributeMaxDynamicSharedMemorySize,
                         (int)smem);
    lstm_rec<<<NCTA_REC, 256, smem>>>(W, h0, c0, out);
}

// round 14
// speedup vs baseline: 1.1054x; 1.1054x over previous
#include <cuda_runtime.h>
#include <cuda_bf16.h>
#include <mma.h>
#include <math.h>

#define B_  32
#define T_  2048
#define D_  512
#define H_  512
#define G_  2048
#define BT_ 65536
#define NCTA_REC 128

using namespace nvcuda;

__device__ float g_xg[65536ULL * 2048ULL];
__device__ float g_h[2][B_ * H_];
__device__ unsigned g_flags[NCTA_REC];
__device__ unsigned g_go;

__device__ __nv_bfloat16 g_xhi[65536ULL * 512ULL];
__device__ __nv_bfloat16 g_xlo[65536ULL * 512ULL];
__device__ __nv_bfloat16 g_whi[512 * 2048];
__device__ __nv_bfloat16 g_wlo[512 * 2048];

__device__ __forceinline__ unsigned ld_acq_u32(const unsigned* p)
{
    unsigned v;
    asm volatile("ld.acquire.gpu.global.u32 %0, [%1];" : "=r"(v) : "l"(p));
    return v;
}

__device__ __forceinline__ void st_rel_u32(unsigned* p, unsigned v)
{
    asm volatile("st.release.gpu.global.u32 [%0], %1;" :: "l"(p), "r"(v));
}

__device__ __forceinline__ float dot4(float acc, float4 h, float4 w)
{
    return fmaf(h.x, w.x, fmaf(h.y, w.y, fmaf(h.z, w.z, fmaf(h.w, w.w, acc))));
}

// ---------------------------------------------------------------------------
// Kernel A0: split x and Wx into bf16 hi/lo
// ---------------------------------------------------------------------------
__global__ __launch_bounds__(256) void cvt_split(const float* __restrict__ x,
                                                 const float* __restrict__ W)
{
    const size_t stride = (size_t)gridDim.x * blockDim.x;
    const size_t i0 = (size_t)blockIdx.x * blockDim.x + threadIdx.x;
    for (size_t i = i0; i < 65536ULL * 512ULL; i += stride) {
        float v = x[i];
        __nv_bfloat16 hv = __float2bfloat16(v);
        g_xhi[i] = hv;
        g_xlo[i] = __float2bfloat16(v - __bfloat162float(hv));
    }
    for (size_t i = i0; i < (size_t)(512 * 2048); i += stride) {
        float v = W[i];
        __nv_bfloat16 hv = __float2bfloat16(v);
        g_whi[i] = hv;
        g_wlo[i] = __float2bfloat16(v - __bfloat162float(hv));
    }
}

// ---------------------------------------------------------------------------
// Kernel A: xg = x @ Wx + b via bf16 hi/lo WMMA GEMM (no inline asm).
// 128x128 tile, BK=16, 8 warps = 2(m) x 4(n), warp tile 64x32.
// C = Ahi*Bhi + Ahi*Blo + Alo*Bhi in fp32 accumulators.
// ---------------------------------------------------------------------------
#define ASTR 24
#define BSTR 136
#define CSTR 132

typedef wmma::fragment<wmma::matrix_a, 16, 16, 16, __nv_bfloat16, wmma::row_major> AFrag;
typedef wmma::fragment<wmma::matrix_b, 16, 16, 16, __nv_bfloat16, wmma::row_major> BFrag;
typedef wmma::fragment<wmma::accumulator, 16, 16, 16, float> CFrag;

__global__ __launch_bounds__(256) void xg_gemm_tc(const float* __restrict__ bias)
{
    extern __shared__ char smx[];
    __nv_bfloat16* Ah = (__nv_bfloat16*)smx;
    __nv_bfloat16* Al = Ah + 128 * ASTR;
    __nv_bfloat16* Bh = Al + 128 * ASTR;
    __nv_bfloat16* Bl = Bh + 16 * BSTR;
    float* stage = (float*)smx;

    const int tid = threadIdx.x;
    const int wid = tid >> 5;
    const int wm  = wid & 1;
    const int wn  = wid >> 1;
    const int rowBase = blockIdx.y * 128;
    const int colBase = blockIdx.x * 128;

    CFrag c[4][2];
#pragma unroll
    for (int mt = 0; mt < 4; mt++) {
#pragma unroll
        for (int nt = 0; nt < 2; nt++) {
            wmma::fill_fragment(c[mt][nt], 0.f);
        }
    }

    const int ar = tid >> 1;
    const int ac = (tid & 1) * 8;
    const int br = tid >> 4;
    const int bc = (tid & 15) * 8;
    const __nv_bfloat16* xh = g_xhi + (size_t)(rowBase + ar) * 512 + ac;
    const __nv_bfloat16* xl = g_xlo + (size_t)(rowBase + ar) * 512 + ac;
    const __nv_bfloat16* wh = g_whi + (size_t)br * 2048 + colBase + bc;
    const __nv_bfloat16* wl = g_wlo + (size_t)br * 2048 + colBase + bc;

    for (int k0 = 0; k0 < 512; k0 += 16) {
        *(uint4*)(Ah + ar * ASTR + ac) = *(const uint4*)(xh + k0);
        *(uint4*)(Al + ar * ASTR + ac) = *(const uint4*)(xl + k0);
        *(uint4*)(Bh + br * BSTR + bc) = *(const uint4*)(wh + (size_t)k0 * 2048);
        *(uint4*)(Bl + br * BSTR + bc) = *(const uint4*)(wl + (size_t)k0 * 2048);
        __syncthreads();

#pragma unroll
        for (int nt = 0; nt < 2; nt++) {
            BFrag bh;
            BFrag bl;
            wmma::load_matrix_sync(bh, Bh + wn * 32 + nt * 16, BSTR);
            wmma::load_matrix_sync(bl, Bl + wn * 32 + nt * 16, BSTR);
#pragma unroll
            for (int mt = 0; mt < 4; mt++) {
                AFrag ah;
                AFrag al;
                wmma::load_matrix_sync(ah, Ah + (wm * 64 + mt * 16) * ASTR, ASTR);
                wmma::load_matrix_sync(al, Al + (wm * 64 + mt * 16) * ASTR, ASTR);
                wmma::mma_sync(c[mt][nt], ah, bh, c[mt][nt]);
                wmma::mma_sync(c[mt][nt], ah, bl, c[mt][nt]);
                wmma::mma_sync(c[mt][nt], al, bh, c[mt][nt]);
            }
        }
        __syncthreads();
    }

    // Stage accumulators in SMEM, then bias-add + coalesced scatter to g_xg.
#pragma unroll
    for (int mt = 0; mt < 4; mt++) {
#pragma unroll
        for (int nt = 0; nt < 2; nt++) {
            float* sp = stage + (wm * 64 + mt * 16) * CSTR + wn * 32 + nt * 16;
            wmma::store_matrix_sync(sp, c[mt][nt], CSTR, wmma::mem_row_major);
        }
    }
    __syncthreads();

    for (int idx = tid; idx < 128 * 32; idx += 256) {
        int row = idx >> 5;
        int c4  = (idx & 31) * 4;
        int r = rowBase + row;
        int t = r & (T_ - 1);
        int bb = r >> 11;
        float4 v = *(const float4*)(stage + row * CSTR + c4);
        const float* bp = bias + colBase + c4;
        v.x += bp[0];
        v.y += bp[1];
        v.z += bp[2];
        v.w += bp[3];
        *(float4*)(g_xg + ((size_t)t * B_ + bb) * G_ + colBase + c4) = v;
    }
}

// ---------------------------------------------------------------------------
// Kernel B: persistent recurrence (round-8 winner; dot phase loop-ified,
// identical fmaf order).
// ---------------------------------------------------------------------------
#define WSTRIDE  516
#define SM_W     0
#define SM_HS    (16 * WSTRIDE)
#define SM_PART  (SM_HS + 32 * WSTRIDE)
#define PART_BQ  20
#define PART_BB  164
#define SM_CS    (SM_PART + 32 * PART_BB)
#define SMEM_FLOATS (SM_CS + 128)

__global__ __launch_bounds__(256) void lstm_rec(const float* __restrict__ W,
                                                const float* __restrict__ h0,
                                                const float* __restrict__ c0,
                                                float* __restrict__ out)
{
    extern __shared__ float sm[];
    float* Wsm  = sm + SM_W;
    float* hs   = sm + SM_HS;
    float* part = sm + SM_PART;
    float* cs   = sm + SM_CS;

    const int tid = threadIdx.x;
    const int j   = blockIdx.x;
    const int jb  = j * 4;

    for (int e = tid; e < 8192; e += 256) {
        int k  = e >> 4;
        int gl = e & 15;
        int gcol = (gl >> 2) * 512 + jb + (gl & 3);
        Wsm[gl * WSTRIDE + k] = W[(size_t)(512 + k) * 2048 + gcol];
    }
    if (tid < 128) {
        int bb = tid >> 2;
        int hc = tid & 3;
        cs[hc * 32 + bb] = c0[bb * 512 + jb + hc];
    }
    __shared__ unsigned s_fb;
    __shared__ unsigned s_gb;
    if (tid == 0) {
        s_fb = *(volatile unsigned*)&g_flags[j];
        s_gb = *(volatile unsigned*)&g_go;
    }
    __syncthreads();
    const unsigned fbase = s_fb;
    const unsigned gbase = s_gb;

    const int bq = tid >> 5;
    const int gq = (tid >> 3) & 3;
    const int kq = tid & 7;
    const float* hbp = hs + (bq * 4) * WSTRIDE;
    const float* wbp = Wsm + (gq * 4) * WSTRIDE;
    const int kb = kq * 64;
    float* pst = part + kq * PART_BQ + gq * 4;

    const int cb  = tid >> 2;
    const int hcl = tid & 3;

    for (int t = 0; t < T_; t++) {
        float gx[4];
        gx[0] = 0.f;
        gx[1] = 0.f;
        gx[2] = 0.f;
        gx[3] = 0.f;
        if (tid < 128) {
            const float* xp = g_xg + ((size_t)t * B_ + cb) * G_ + jb + hcl;
#pragma unroll
            for (int q = 0; q < 4; q++) {
                gx[q] = xp[q * 512];
            }
        }

        const float* hsrc = (t == 0) ? h0 : g_h[t & 1];
        for (int i4 = tid; i4 < 4096; i4 += 256) {
            int bb2 = i4 >> 7;
            int k4 = (i4 & 127) * 4;
            *(float4*)(hs + bb2 * WSTRIDE + k4) = *(const float4*)(hsrc + bb2 * 512 + k4);
        }
        __syncthreads();

        float av[16];
#pragma unroll
        for (int z = 0; z < 16; z++) {
            av[z] = 0.f;
        }
#pragma unroll 4
        for (int i = 0; i < 16; i++) {
            int ko = kb + (((i + kq) & 15) << 2);
            float4 hv[4];
            float4 wv[4];
#pragma unroll
            for (int r = 0; r < 4; r++) {
                hv[r] = *(const float4*)(hbp + r * WSTRIDE + ko);
                wv[r] = *(const float4*)(wbp + r * WSTRIDE + ko);
            }
#pragma unroll
            for (int r = 0; r < 4; r++) {
#pragma unroll
                for (int c4 = 0; c4 < 4; c4++) {
                    av[r * 4 + c4] = dot4(av[r * 4 + c4], hv[r], wv[c4]);
                }
            }
        }
#pragma unroll
        for (int r = 0; r < 4; r++) {
            float4 pv = make_float4(av[r * 4 + 0], av[r * 4 + 1],
                                    av[r * 4 + 2], av[r * 4 + 3]);
            *(float4*)(pst + (4 * bq + r) * PART_BB) = pv;
        }
        __syncthreads();

        if (tid < 128) {
            float s0 = gx[0];
            float s1 = gx[1];
            float s2 = gx[2];
            float s3 = gx[3];
            const float* pb = part + cb * PART_BB + hcl;
#pragma unroll
            for (int q = 0; q < 8; q++) {
                s0 += pb[q * PART_BQ + 0];
                s1 += pb[q * PART_BQ + 4];
                s2 += pb[q * PART_BQ + 8];
                s3 += pb[q * PART_BQ + 12];
            }
            float iv = 1.f / (1.f + expf(-s0));
            float fv = 1.f / (1.f + expf(-s1));
            float gv = tanhf(s2);
            float ov = 1.f / (1.f + expf(-s3));
            float cc = fv * cs[hcl * 32 + cb] + iv * gv;
            cs[hcl * 32 + cb] = cc;
            float hh = ov * tanhf(cc);
            g_h[(t + 1) & 1][cb * 512 + jb + hcl] = hh;
            out[((size_t)cb * T_ + t) * H_ + jb + hcl] = hh;
            if (t == T_ - 1) {
                out[(size_t)BT_ * H_ + cb * 512 + jb + hcl] = hh;
                out[(size_t)BT_ * H_ + B_ * H_ + cb * 512 + jb + hcl] = cc;
            }
        }
        __syncthreads();

        if (t < T_ - 1) {
            const unsigned step = (unsigned)t + 1u;
            if (tid == 0) {
                st_rel_u32(&g_flags[j], fbase + step);
            }
            if (j == 0) {
                if (tid < NCTA_REC) {
                    while ((int)(ld_acq_u32(&g_flags[tid]) - (fbase + step)) < 0) { }
                }
                __syncthreads();
                if (tid == 0) {
                    st_rel_u32(&g_go, gbase + step);
                }
            } else {
                if (tid == 0) {
                    while ((int)(ld_acq_u32(&g_go) - (gbase + step)) < 0) { }
                }
                __syncthreads();
            }
        }
    }
}

// ---------------------------------------------------------------------------
// Launcher
// ---------------------------------------------------------------------------
extern "C" void kernel_launch(void* const* d_in, const int* in_sizes, int n_in,
                              void* d_out, int out_size)
{
    const float* x    = (const float*)d_in[0];
    const float* W    = (const float*)d_in[1];
    const float* bias = (const float*)d_in[2];
    const float* h0   = (const float*)d_in[3];
    const float* c0   = (const float*)d_in[4];
    float* out = (float*)d_out;

    cvt_split<<<2048, 256>>>(x, W);

    size_t gemm_smem = 128 * CSTR * sizeof(float);   // 67.6 KB staging (aliases A/B)
    cudaFuncSetAttribute(xg_gemm_tc, cudaFuncAttributeMaxDynamicSharedMemorySize,
                         (int)gemm_smem);
    dim3 grid(G_ / 128, BT_ / 128);
    xg_gemm_tc<<<grid, 256, gemm_smem>>>(bias);

    size_t smem = SMEM_FLOATS * sizeof(float);
    cudaFuncSetAttribute(lstm_rec, cudaFuncAttributeMaxDynamicSharedMemorySize,
                         (int)smem);
    lstm_rec<<<NCTA_REC, 256, smem>>>(W, h0, c0, out);
}

// round 15
// speedup vs baseline: 1.1088x; 1.0030x over previous
#include <cuda_runtime.h>
#include <cuda_bf16.h>
#include <cuda_pipeline.h>
#include <mma.h>
#include <math.h>

#define B_  32
#define T_  2048
#define D_  512
#define H_  512
#define G_  2048
#define BT_ 65536
#define NCTA_REC 128

using namespace nvcuda;

__device__ float g_xg[65536ULL * 2048ULL];
__device__ float g_h[2][B_ * H_];
__device__ unsigned g_flags[NCTA_REC];
__device__ unsigned g_go;

__device__ __nv_bfloat16 g_xhi[65536ULL * 512ULL];
__device__ __nv_bfloat16 g_xlo[65536ULL * 512ULL];
__device__ __nv_bfloat16 g_whi[512 * 2048];
__device__ __nv_bfloat16 g_wlo[512 * 2048];

__device__ __forceinline__ unsigned ld_acq_u32(const unsigned* p)
{
    unsigned v;
    asm volatile("ld.acquire.gpu.global.u32 %0, [%1];" : "=r"(v) : "l"(p));
    return v;
}

__device__ __forceinline__ void st_rel_u32(unsigned* p, unsigned v)
{
    asm volatile("st.release.gpu.global.u32 [%0], %1;" :: "l"(p), "r"(v));
}

__device__ __forceinline__ float dot4(float acc, float4 h, float4 w)
{
    return fmaf(h.x, w.x, fmaf(h.y, w.y, fmaf(h.z, w.z, fmaf(h.w, w.w, acc))));
}

// ---------------------------------------------------------------------------
// Kernel A0: split x and Wx into bf16 hi/lo
// ---------------------------------------------------------------------------
__global__ __launch_bounds__(256) void cvt_split(const float* __restrict__ x,
                                                 const float* __restrict__ W)
{
    const size_t stride = (size_t)gridDim.x * blockDim.x;
    const size_t i0 = (size_t)blockIdx.x * blockDim.x + threadIdx.x;
    for (size_t i = i0; i < 65536ULL * 512ULL; i += stride) {
        float v = x[i];
        __nv_bfloat16 hv = __float2bfloat16(v);
        g_xhi[i] = hv;
        g_xlo[i] = __float2bfloat16(v - __bfloat162float(hv));
    }
    for (size_t i = i0; i < (size_t)(512 * 2048); i += stride) {
        float v = W[i];
        __nv_bfloat16 hv = __float2bfloat16(v);
        g_whi[i] = hv;
        g_wlo[i] = __float2bfloat16(v - __bfloat162float(hv));
    }
}

// ---------------------------------------------------------------------------
// Kernel A: xg = x @ Wx + b via bf16 hi/lo WMMA GEMM.
// NEW: 2-stage cp.async double buffer + hoisted A fragments.
// 128x128 tile, BK=16, 8 warps = 2(m) x 4(n), warp tile 64x32.
// ---------------------------------------------------------------------------
#define ASTR 24
#define BSTR 136
#define CSTR 132
#define A_BUF_BYTES (128 * ASTR * 2)
#define B_BUF_BYTES (16 * BSTR * 2)

typedef wmma::fragment<wmma::matrix_a, 16, 16, 16, __nv_bfloat16, wmma::row_major> AFrag;
typedef wmma::fragment<wmma::matrix_b, 16, 16, 16, __nv_bfloat16, wmma::row_major> BFrag;
typedef wmma::fragment<wmma::accumulator, 16, 16, 16, float> CFrag;

__global__ __launch_bounds__(256) void xg_gemm_tc(const float* __restrict__ bias)
{
    extern __shared__ char smx[];
    // Double-buffered tiles (bytes):
    //  Ah: [0, 2*A_BUF)   Al: [2*A_BUF, 4*A_BUF)
    //  Bh: [4*A_BUF, 4*A_BUF+2*B_BUF)   Bl: next 2*B_BUF
    __nv_bfloat16* AhS[2];
    __nv_bfloat16* AlS[2];
    __nv_bfloat16* BhS[2];
    __nv_bfloat16* BlS[2];
    AhS[0] = (__nv_bfloat16*)(smx);
    AhS[1] = (__nv_bfloat16*)(smx + A_BUF_BYTES);
    AlS[0] = (__nv_bfloat16*)(smx + 2 * A_BUF_BYTES);
    AlS[1] = (__nv_bfloat16*)(smx + 3 * A_BUF_BYTES);
    BhS[0] = (__nv_bfloat16*)(smx + 4 * A_BUF_BYTES);
    BhS[1] = (__nv_bfloat16*)(smx + 4 * A_BUF_BYTES + B_BUF_BYTES);
    BlS[0] = (__nv_bfloat16*)(smx + 4 * A_BUF_BYTES + 2 * B_BUF_BYTES);
    BlS[1] = (__nv_bfloat16*)(smx + 4 * A_BUF_BYTES + 3 * B_BUF_BYTES);
    float* stage = (float*)smx;

    const int tid = threadIdx.x;
    const int wid = tid >> 5;
    const int wm  = wid & 1;
    const int wn  = wid >> 1;
    const int rowBase = blockIdx.y * 128;
    const int colBase = blockIdx.x * 128;

    CFrag c[4][2];
#pragma unroll
    for (int mt = 0; mt < 4; mt++) {
#pragma unroll
        for (int nt = 0; nt < 2; nt++) {
            wmma::fill_fragment(c[mt][nt], 0.f);
        }
    }

    const int ar = tid >> 1;
    const int ac = (tid & 1) * 8;
    const int br = tid >> 4;
    const int bc = (tid & 15) * 8;
    const __nv_bfloat16* xh = g_xhi + (size_t)(rowBase + ar) * 512 + ac;
    const __nv_bfloat16* xl = g_xlo + (size_t)(rowBase + ar) * 512 + ac;
    const __nv_bfloat16* wh = g_whi + (size_t)br * 2048 + colBase + bc;
    const __nv_bfloat16* wl = g_wlo + (size_t)br * 2048 + colBase + bc;
    const int adst = ar * ASTR + ac;
    const int bdst = br * BSTR + bc;

    // Prologue: stage 0 loads
    __pipeline_memcpy_async(AhS[0] + adst, xh, 16);
    __pipeline_memcpy_async(AlS[0] + adst, xl, 16);
    __pipeline_memcpy_async(BhS[0] + bdst, wh, 16);
    __pipeline_memcpy_async(BlS[0] + bdst, wl, 16);
    __pipeline_commit();

    for (int i = 0; i < 32; i++) {
        if (i + 1 < 32) {
            const int s = (i + 1) & 1;
            const int k0 = (i + 1) * 16;
            __pipeline_memcpy_async(AhS[s] + adst, xh + k0, 16);
            __pipeline_memcpy_async(AlS[s] + adst, xl + k0, 16);
            __pipeline_memcpy_async(BhS[s] + bdst, wh + (size_t)k0 * 2048, 16);
            __pipeline_memcpy_async(BlS[s] + bdst, wl + (size_t)k0 * 2048, 16);
            __pipeline_commit();
            __pipeline_wait_prior(1);
        } else {
            __pipeline_wait_prior(0);
        }
        __syncthreads();

        const int s = i & 1;
        AFrag ah[4];
        AFrag al[4];
#pragma unroll
        for (int mt = 0; mt < 4; mt++) {
            wmma::load_matrix_sync(ah[mt], AhS[s] + (wm * 64 + mt * 16) * ASTR, ASTR);
            wmma::load_matrix_sync(al[mt], AlS[s] + (wm * 64 + mt * 16) * ASTR, ASTR);
        }
#pragma unroll
        for (int nt = 0; nt < 2; nt++) {
            BFrag bh;
            BFrag bl;
            wmma::load_matrix_sync(bh, BhS[s] + wn * 32 + nt * 16, BSTR);
            wmma::load_matrix_sync(bl, BlS[s] + wn * 32 + nt * 16, BSTR);
#pragma unroll
            for (int mt = 0; mt < 4; mt++) {
                wmma::mma_sync(c[mt][nt], ah[mt], bh, c[mt][nt]);
                wmma::mma_sync(c[mt][nt], ah[mt], bl, c[mt][nt]);
                wmma::mma_sync(c[mt][nt], al[mt], bh, c[mt][nt]);
            }
        }
        __syncthreads();
    }

    // Stage accumulators in SMEM, then bias-add + coalesced scatter to g_xg.
#pragma unroll
    for (int mt = 0; mt < 4; mt++) {
#pragma unroll
        for (int nt = 0; nt < 2; nt++) {
            float* sp = stage + (wm * 64 + mt * 16) * CSTR + wn * 32 + nt * 16;
            wmma::store_matrix_sync(sp, c[mt][nt], CSTR, wmma::mem_row_major);
        }
    }
    __syncthreads();

    for (int idx = tid; idx < 128 * 32; idx += 256) {
        int row = idx >> 5;
        int c4  = (idx & 31) * 4;
        int r = rowBase + row;
        int t = r & (T_ - 1);
        int bb = r >> 11;
        float4 v = *(const float4*)(stage + row * CSTR + c4);
        const float* bp = bias + colBase + c4;
        v.x += bp[0];
        v.y += bp[1];
        v.z += bp[2];
        v.w += bp[3];
        *(float4*)(g_xg + ((size_t)t * B_ + bb) * G_ + colBase + c4) = v;
    }
}

// ---------------------------------------------------------------------------
// Kernel B: persistent recurrence (round-8 winner; loop-ified dot phase).
// ---------------------------------------------------------------------------
#define WSTRIDE  516
#define SM_W     0
#define SM_HS    (16 * WSTRIDE)
#define SM_PART  (SM_HS + 32 * WSTRIDE)
#define PART_BQ  20
#define PART_BB  164
#define SM_CS    (SM_PART + 32 * PART_BB)
#define SMEM_FLOATS (SM_CS + 128)

__global__ __launch_bounds__(256) void lstm_rec(const float* __restrict__ W,
                                                const float* __restrict__ h0,
                                                const float* __restrict__ c0,
                                                float* __restrict__ out)
{
    extern __shared__ float sm[];
    float* Wsm  = sm + SM_W;
    float* hs   = sm + SM_HS;
    float* part = sm + SM_PART;
    float* cs   = sm + SM_CS;

    const int tid = threadIdx.x;
    const int j   = blockIdx.x;
    const int jb  = j * 4;

    for (int e = tid; e < 8192; e += 256) {
        int k  = e >> 4;
        int gl = e & 15;
        int gcol = (gl >> 2) * 512 + jb + (gl & 3);
        Wsm[gl * WSTRIDE + k] = W[(size_t)(512 + k) * 2048 + gcol];
    }
    if (tid < 128) {
        int bb = tid >> 2;
        int hc = tid & 3;
        cs[hc * 32 + bb] = c0[bb * 512 + jb + hc];
    }
    __shared__ unsigned s_fb;
    __shared__ unsigned s_gb;
    if (tid == 0) {
        s_fb = *(volatile unsigned*)&g_flags[j];
        s_gb = *(volatile unsigned*)&g_go;
    }
    __syncthreads();
    const unsigned fbase = s_fb;
    const unsigned gbase = s_gb;

    const int bq = tid >> 5;
    const int gq = (tid >> 3) & 3;
    const int kq = tid & 7;
    const float* hbp = hs + (bq * 4) * WSTRIDE;
    const float* wbp = Wsm + (gq * 4) * WSTRIDE;
    const int kb = kq * 64;
    float* pst = part + kq * PART_BQ + gq * 4;

    const int cb  = tid >> 2;
    const int hcl = tid & 3;

    for (int t = 0; t < T_; t++) {
        float gx[4];
        gx[0] = 0.f;
        gx[1] = 0.f;
        gx[2] = 0.f;
        gx[3] = 0.f;
        if (tid < 128) {
            const float* xp = g_xg + ((size_t)t * B_ + cb) * G_ + jb + hcl;
#pragma unroll
            for (int q = 0; q < 4; q++) {
                gx[q] = xp[q * 512];
            }
        }

        const float* hsrc = (t == 0) ? h0 : g_h[t & 1];
        for (int i4 = tid; i4 < 4096; i4 += 256) {
            int bb2 = i4 >> 7;
            int k4 = (i4 & 127) * 4;
            *(float4*)(hs + bb2 * WSTRIDE + k4) = *(const float4*)(hsrc + bb2 * 512 + k4);
        }
        __syncthreads();

        float av[16];
#pragma unroll
        for (int z = 0; z < 16; z++) {
            av[z] = 0.f;
        }
#pragma unroll 4
        for (int i = 0; i < 16; i++) {
            int ko = kb + (((i + kq) & 15) << 2);
            float4 hv[4];
            float4 wv[4];
#pragma unroll
            for (int r = 0; r < 4; r++) {
                hv[r] = *(const float4*)(hbp + r * WSTRIDE + ko);
                wv[r] = *(const float4*)(wbp + r * WSTRIDE + ko);
            }
#pragma unroll
            for (int r = 0; r < 4; r++) {
#pragma unroll
                for (int c4 = 0; c4 < 4; c4++) {
                    av[r * 4 + c4] = dot4(av[r * 4 + c4], hv[r], wv[c4]);
                }
            }
        }
#pragma unroll
        for (int r = 0; r < 4; r++) {
            float4 pv = make_float4(av[r * 4 + 0], av[r * 4 + 1],
                                    av[r * 4 + 2], av[r * 4 + 3]);
            *(float4*)(pst + (4 * bq + r) * PART_BB) = pv;
        }
        __syncthreads();

        if (tid < 128) {
            float s0 = gx[0];
            float s1 = gx[1];
            float s2 = gx[2];
            float s3 = gx[3];
            const float* pb = part + cb * PART_BB + hcl;
#pragma unroll
            for (int q = 0; q < 8; q++) {
                s0 += pb[q * PART_BQ + 0];
                s1 += pb[q * PART_BQ + 4];
                s2 += pb[q * PART_BQ + 8];
                s3 += pb[q * PART_BQ + 12];
            }
            float iv = 1.f / (1.f + expf(-s0));
            float fv = 1.f / (1.f + expf(-s1));
            float gv = tanhf(s2);
            float ov = 1.f / (1.f + expf(-s3));
            float cc = fv * cs[hcl * 32 + cb] + iv * gv;
            cs[hcl * 32 + cb] = cc;
            float hh = ov * tanhf(cc);
            g_h[(t + 1) & 1][cb * 512 + jb + hcl] = hh;
            out[((size_t)cb * T_ + t) * H_ + jb + hcl] = hh;
            if (t == T_ - 1) {
                out[(size_t)BT_ * H_ + cb * 512 + jb + hcl] = hh;
                out[(size_t)BT_ * H_ + B_ * H_ + cb * 512 + jb + hcl] = cc;
            }
        }
        __syncthreads();

        if (t < T_ - 1) {
            const unsigned step = (unsigned)t + 1u;
            if (tid == 0) {
                st_rel_u32(&g_flags[j], fbase + step);
            }
            if (j == 0) {
                if (tid < NCTA_REC) {
                    while ((int)(ld_acq_u32(&g_flags[tid]) - (fbase + step)) < 0) { }
                }
                __syncthreads();
                if (tid == 0) {
                    st_rel_u32(&g_go, gbase + step);
                }
            } else {
                if (tid == 0) {
                    while ((int)(ld_acq_u32(&g_go) - (gbase + step)) < 0) { }
                }
                __syncthreads();
            }
        }
    }
}

// ---------------------------------------------------------------------------
// Launcher
// ---------------------------------------------------------------------------
extern "C" void kernel_launch(void* const* d_in, const int* in_sizes, int n_in,
                              void* d_out, int out_size)
{
    const float* x    = (const float*)d_in[0];
    const float* W    = (const float*)d_in[1];
    const float* bias = (const float*)d_in[2];
    const float* h0   = (const float*)d_in[3];
    const float* c0   = (const float*)d_in[4];
    float* out = (float*)d_out;

    cvt_split<<<2048, 256>>>(x, W);

    size_t gemm_smem = 128 * CSTR * sizeof(float);   // 67.6 KB (tiles alias stage)
    cudaFuncSetAttribute(xg_gemm_tc, cudaFuncAttributeMaxDynamicSharedMemorySize,
                         (int)gemm_smem);
    dim3 grid(G_ / 128, BT_ / 128);
    xg_gemm_tc<<<grid, 256, gemm_smem>>>(bias);

    size_t smem = SMEM_FLOATS * sizeof(float);
    cudaFuncSetAttribute(lstm_rec, cudaFuncAttributeMaxDynamicSharedMemorySize,
                         (int)smem);
    lstm_rec<<<NCTA_REC, 256, smem>>>(W, h0, c0, out);
}

// round 16
// speedup vs baseline: 1.2628x; 1.1389x over previous
#include <cuda_runtime.h>
#include <cuda_bf16.h>
#include <cuda_pipeline.h>
#include <mma.h>
#include <math.h>

#define B_  32
#define T_  2048
#define D_  512
#define H_  512
#define G_  2048
#define BT_ 65536
#define NCTA_REC 128

using namespace nvcuda;

__device__ float g_xg[65536ULL * 2048ULL];
__device__ float g_h[2][B_ * H_];
__device__ unsigned g_flags[NCTA_REC];
__device__ unsigned g_go;

__device__ __nv_bfloat16 g_xhi[65536ULL * 512ULL];
__device__ __nv_bfloat16 g_xlo[65536ULL * 512ULL];
__device__ __nv_bfloat16 g_whi[512 * 2048];
__device__ __nv_bfloat16 g_wlo[512 * 2048];

__device__ __forceinline__ unsigned ld_acq_u32(const unsigned* p)
{
    unsigned v;
    asm volatile("ld.acquire.gpu.global.u32 %0, [%1];" : "=r"(v) : "l"(p));
    return v;
}

__device__ __forceinline__ void st_rel_u32(unsigned* p, unsigned v)
{
    asm volatile("st.release.gpu.global.u32 [%0], %1;" :: "l"(p), "r"(v));
}

// ---------------------------------------------------------------------------
// Kernel A0: split x and Wx into bf16 hi/lo
// ---------------------------------------------------------------------------
__global__ __launch_bounds__(256) void cvt_split(const float* __restrict__ x,
                                                 const float* __restrict__ W)
{
    const size_t stride = (size_t)gridDim.x * blockDim.x;
    const size_t i0 = (size_t)blockIdx.x * blockDim.x + threadIdx.x;
    for (size_t i = i0; i < 65536ULL * 512ULL; i += stride) {
        float v = x[i];
        __nv_bfloat16 hv = __float2bfloat16(v);
        g_xhi[i] = hv;
        g_xlo[i] = __float2bfloat16(v - __bfloat162float(hv));
    }
    for (size_t i = i0; i < (size_t)(512 * 2048); i += stride) {
        float v = W[i];
        __nv_bfloat16 hv = __float2bfloat16(v);
        g_whi[i] = hv;
        g_wlo[i] = __float2bfloat16(v - __bfloat162float(hv));
    }
}

// ---------------------------------------------------------------------------
// Kernel A: xg = x @ Wx + b via bf16 hi/lo WMMA GEMM (round-15 version).
// ---------------------------------------------------------------------------
#define ASTR 24
#define BSTR 136
#define CSTR 132
#define A_BUF_BYTES (128 * ASTR * 2)
#define B_BUF_BYTES (16 * BSTR * 2)

typedef wmma::fragment<wmma::matrix_a, 16, 16, 16, __nv_bfloat16, wmma::row_major> AFrag;
typedef wmma::fragment<wmma::matrix_b, 16, 16, 16, __nv_bfloat16, wmma::row_major> BFrag;
typedef wmma::fragment<wmma::accumulator, 16, 16, 16, float> CFrag;

__global__ __launch_bounds__(256) void xg_gemm_tc(const float* __restrict__ bias)
{
    extern __shared__ char smx[];
    __nv_bfloat16* AhS[2];
    __nv_bfloat16* AlS[2];
    __nv_bfloat16* BhS[2];
    __nv_bfloat16* BlS[2];
    AhS[0] = (__nv_bfloat16*)(smx);
    AhS[1] = (__nv_bfloat16*)(smx + A_BUF_BYTES);
    AlS[0] = (__nv_bfloat16*)(smx + 2 * A_BUF_BYTES);
    AlS[1] = (__nv_bfloat16*)(smx + 3 * A_BUF_BYTES);
    BhS[0] = (__nv_bfloat16*)(smx + 4 * A_BUF_BYTES);
    BhS[1] = (__nv_bfloat16*)(smx + 4 * A_BUF_BYTES + B_BUF_BYTES);
    BlS[0] = (__nv_bfloat16*)(smx + 4 * A_BUF_BYTES + 2 * B_BUF_BYTES);
    BlS[1] = (__nv_bfloat16*)(smx + 4 * A_BUF_BYTES + 3 * B_BUF_BYTES);
    float* stage = (float*)smx;

    const int tid = threadIdx.x;
    const int wid = tid >> 5;
    const int wm  = wid & 1;
    const int wn  = wid >> 1;
    const int rowBase = blockIdx.y * 128;
    const int colBase = blockIdx.x * 128;

    CFrag c[4][2];
#pragma unroll
    for (int mt = 0; mt < 4; mt++) {
#pragma unroll
        for (int nt = 0; nt < 2; nt++) {
            wmma::fill_fragment(c[mt][nt], 0.f);
        }
    }

    const int ar = tid >> 1;
    const int ac = (tid & 1) * 8;
    const int br = tid >> 4;
    const int bc = (tid & 15) * 8;
    const __nv_bfloat16* xh = g_xhi + (size_t)(rowBase + ar) * 512 + ac;
    const __nv_bfloat16* xl = g_xlo + (size_t)(rowBase + ar) * 512 + ac;
    const __nv_bfloat16* wh = g_whi + (size_t)br * 2048 + colBase + bc;
    const __nv_bfloat16* wl = g_wlo + (size_t)br * 2048 + colBase + bc;
    const int adst = ar * ASTR + ac;
    const int bdst = br * BSTR + bc;

    __pipeline_memcpy_async(AhS[0] + adst, xh, 16);
    __pipeline_memcpy_async(AlS[0] + adst, xl, 16);
    __pipeline_memcpy_async(BhS[0] + bdst, wh, 16);
    __pipeline_memcpy_async(BlS[0] + bdst, wl, 16);
    __pipeline_commit();

    for (int i = 0; i < 32; i++) {
        if (i + 1 < 32) {
            const int s = (i + 1) & 1;
            const int k0 = (i + 1) * 16;
            __pipeline_memcpy_async(AhS[s] + adst, xh + k0, 16);
            __pipeline_memcpy_async(AlS[s] + adst, xl + k0, 16);
            __pipeline_memcpy_async(BhS[s] + bdst, wh + (size_t)k0 * 2048, 16);
            __pipeline_memcpy_async(BlS[s] + bdst, wl + (size_t)k0 * 2048, 16);
            __pipeline_commit();
            __pipeline_wait_prior(1);
        } else {
            __pipeline_wait_prior(0);
        }
        __syncthreads();

        const int s = i & 1;
        AFrag ah[4];
        AFrag al[4];
#pragma unroll
        for (int mt = 0; mt < 4; mt++) {
            wmma::load_matrix_sync(ah[mt], AhS[s] + (wm * 64 + mt * 16) * ASTR, ASTR);
            wmma::load_matrix_sync(al[mt], AlS[s] + (wm * 64 + mt * 16) * ASTR, ASTR);
        }
#pragma unroll
        for (int nt = 0; nt < 2; nt++) {
            BFrag bh;
            BFrag bl;
            wmma::load_matrix_sync(bh, BhS[s] + wn * 32 + nt * 16, BSTR);
            wmma::load_matrix_sync(bl, BlS[s] + wn * 32 + nt * 16, BSTR);
#pragma unroll
            for (int mt = 0; mt < 4; mt++) {
                wmma::mma_sync(c[mt][nt], ah[mt], bh, c[mt][nt]);
                wmma::mma_sync(c[mt][nt], ah[mt], bl, c[mt][nt]);
                wmma::mma_sync(c[mt][nt], al[mt], bh, c[mt][nt]);
            }
        }
        __syncthreads();
    }

#pragma unroll
    for (int mt = 0; mt < 4; mt++) {
#pragma unroll
        for (int nt = 0; nt < 2; nt++) {
            float* sp = stage + (wm * 64 + mt * 16) * CSTR + wn * 32 + nt * 16;
            wmma::store_matrix_sync(sp, c[mt][nt], CSTR, wmma::mem_row_major);
        }
    }
    __syncthreads();

    for (int idx = tid; idx < 128 * 32; idx += 256) {
        int row = idx >> 5;
        int c4  = (idx & 31) * 4;
        int r = rowBase + row;
        int t = r & (T_ - 1);
        int bb = r >> 11;
        float4 v = *(const float4*)(stage + row * CSTR + c4);
        const float* bp = bias + colBase + c4;
        v.x += bp[0];
        v.y += bp[1];
        v.z += bp[2];
        v.w += bp[3];
        *(float4*)(g_xg + ((size_t)t * B_ + bb) * G_ + colBase + c4) = v;
    }
}

// ---------------------------------------------------------------------------
// Kernel B: persistent recurrence with WMMA dot phase.
// CTA j owns gate cols gl = gtype*4 + hcl at jb = 4j. Wh slice pre-split to
// bf16 hi/lo in SMEM once. Per step: h broadcast converts fp32 -> bf16 hi/lo;
// 8 warps each take a K=64 segment, compute 32x16 partials via wmma
// (hi*hi + hi*lo + lo*hi), reduce through SMEM; combine + barrier = round-8.
//
// SMEM bytes: hsHi 33792 | hsLo 33792 | wHi 24576 | wLo 24576
//             | part 8*672*4=21504 | cs 512  => 138752 B
// ---------------------------------------------------------------------------
#define HS_STRIDE 528
#define WH_STRIDE 24
#define PART_W    672
#define PART_MT   320
#define PART_LDM  20
#define OFF_HSLO  33792
#define OFF_WHI   67584
#define OFF_WLO   92160
#define OFF_PART  116736
#define OFF_CS    138240
#define REC_SMEM  138752

__global__ __launch_bounds__(256) void lstm_rec(const float* __restrict__ W,
                                                const float* __restrict__ h0,
                                                const float* __restrict__ c0,
                                                float* __restrict__ out)
{
    extern __shared__ char smr[];
    __nv_bfloat16* hsHi = (__nv_bfloat16*)(smr);
    __nv_bfloat16* hsLo = (__nv_bfloat16*)(smr + OFF_HSLO);
    __nv_bfloat16* wHi  = (__nv_bfloat16*)(smr + OFF_WHI);
    __nv_bfloat16* wLo  = (__nv_bfloat16*)(smr + OFF_WLO);
    float* part = (float*)(smr + OFF_PART);
    float* cs   = (float*)(smr + OFF_CS);

    const int tid = threadIdx.x;
    const int wid = tid >> 5;
    const int j   = blockIdx.x;
    const int jb  = j * 4;

    // Load + split Wh slice: wHi/wLo[k*24 + c], c = gtype*4 + hcl
    for (int e = tid; e < 8192; e += 256) {
        int k = e >> 4;
        int c = e & 15;
        int gcol = (c >> 2) * 512 + jb + (c & 3);
        float v = W[(size_t)(512 + k) * 2048 + gcol];
        __nv_bfloat16 hv = __float2bfloat16(v);
        wHi[k * WH_STRIDE + c] = hv;
        wLo[k * WH_STRIDE + c] = __float2bfloat16(v - __bfloat162float(hv));
    }
    if (tid < 128) {
        int bb = tid >> 2;
        int hc = tid & 3;
        cs[hc * 32 + bb] = c0[bb * 512 + jb + hc];
    }
    __shared__ unsigned s_fb;
    __shared__ unsigned s_gb;
    if (tid == 0) {
        s_fb = *(volatile unsigned*)&g_flags[j];
        s_gb = *(volatile unsigned*)&g_go;
    }
    __syncthreads();
    const unsigned fbase = s_fb;
    const unsigned gbase = s_gb;

    const int cb  = tid >> 2;
    const int hcl = tid & 3;

    for (int t = 0; t < T_; t++) {
        float gx[4];
        gx[0] = 0.f;
        gx[1] = 0.f;
        gx[2] = 0.f;
        gx[3] = 0.f;
        if (tid < 128) {
            const float* xp = g_xg + ((size_t)t * B_ + cb) * G_ + jb + hcl;
#pragma unroll
            for (int q = 0; q < 4; q++) {
                gx[q] = xp[q * 512];
            }
        }

        // Broadcast h and convert to bf16 hi/lo in SMEM
        const float* hsrc = (t == 0) ? h0 : g_h[t & 1];
        for (int idx = tid; idx < 4096; idx += 256) {
            int row = idx >> 7;
            int c4  = (idx & 127) * 4;
            float4 v = *(const float4*)(hsrc + row * 512 + c4);
            __nv_bfloat16* ph = hsHi + row * HS_STRIDE + c4;
            __nv_bfloat16* pl = hsLo + row * HS_STRIDE + c4;
            __nv_bfloat16 h0b = __float2bfloat16(v.x);
            __nv_bfloat16 h1b = __float2bfloat16(v.y);
            __nv_bfloat16 h2b = __float2bfloat16(v.z);
            __nv_bfloat16 h3b = __float2bfloat16(v.w);
            ph[0] = h0b;
            ph[1] = h1b;
            ph[2] = h2b;
            ph[3] = h3b;
            pl[0] = __float2bfloat16(v.x - __bfloat162float(h0b));
            pl[1] = __float2bfloat16(v.y - __bfloat162float(h1b));
            pl[2] = __float2bfloat16(v.z - __bfloat162float(h2b));
            pl[3] = __float2bfloat16(v.w - __bfloat162float(h3b));
        }
        __syncthreads();

        // WMMA dot: warp wid handles K segment [64*wid, 64*wid+64)
        {
            CFrag cf[2];
            wmma::fill_fragment(cf[0], 0.f);
            wmma::fill_fragment(cf[1], 0.f);
#pragma unroll
            for (int i = 0; i < 4; i++) {
                int k = wid * 64 + i * 16;
                BFrag bh;
                BFrag bl;
                wmma::load_matrix_sync(bh, wHi + k * WH_STRIDE, WH_STRIDE);
                wmma::load_matrix_sync(bl, wLo + k * WH_STRIDE, WH_STRIDE);
#pragma unroll
                for (int mt = 0; mt < 2; mt++) {
                    AFrag ahh;
                    AFrag alo;
                    wmma::load_matrix_sync(ahh, hsHi + mt * 16 * HS_STRIDE + k, HS_STRIDE);
                    wmma::load_matrix_sync(alo, hsLo + mt * 16 * HS_STRIDE + k, HS_STRIDE);
                    wmma::mma_sync(cf[mt], ahh, bh, cf[mt]);
                    wmma::mma_sync(cf[mt], ahh, bl, cf[mt]);
                    wmma::mma_sync(cf[mt], alo, bh, cf[mt]);
                }
            }
#pragma unroll
            for (int mt = 0; mt < 2; mt++) {
                wmma::store_matrix_sync(part + wid * PART_W + mt * PART_MT,
                                        cf[mt], PART_LDM, wmma::mem_row_major);
            }
        }
        __syncthreads();

        // Combine: thread (cb, hcl) sums 8 warp partials per gate type.
        if (tid < 128) {
            float s0 = gx[0];
            float s1 = gx[1];
            float s2 = gx[2];
            float s3 = gx[3];
            const float* pb = part + (cb >> 4) * PART_MT + (cb & 15) * PART_LDM + hcl;
#pragma unroll
            for (int q = 0; q < 8; q++) {
                const float* pw = pb + q * PART_W;
                s0 += pw[0];
                s1 += pw[4];
                s2 += pw[8];
                s3 += pw[12];
            }
            float iv = 1.f / (1.f + expf(-s0));
            float fv = 1.f / (1.f + expf(-s1));
            float gv = tanhf(s2);
            float ov = 1.f / (1.f + expf(-s3));
            float cc = fv * cs[hcl * 32 + cb] + iv * gv;
            cs[hcl * 32 + cb] = cc;
            float hh = ov * tanhf(cc);
            g_h[(t + 1) & 1][cb * 512 + jb + hcl] = hh;
            out[((size_t)cb * T_ + t) * H_ + jb + hcl] = hh;
            if (t == T_ - 1) {
                out[(size_t)BT_ * H_ + cb * 512 + jb + hcl] = hh;
                out[(size_t)BT_ * H_ + B_ * H_ + cb * 512 + jb + hcl] = cc;
            }
        }
        __syncthreads();

        if (t < T_ - 1) {
            const unsigned step = (unsigned)t + 1u;
            if (tid == 0) {
                st_rel_u32(&g_flags[j], fbase + step);
            }
            if (j == 0) {
                if (tid < NCTA_REC) {
                    while ((int)(ld_acq_u32(&g_flags[tid]) - (fbase + step)) < 0) { }
                }
                __syncthreads();
                if (tid == 0) {
                    st_rel_u32(&g_go, gbase + step);
                }
            } else {
                if (tid == 0) {
                    while ((int)(ld_acq_u32(&g_go) - (gbase + step)) < 0) { }
                }
                __syncthreads();
            }
        }
    }
}

// ---------------------------------------------------------------------------
// Launcher
// ---------------------------------------------------------------------------
extern "C" void kernel_launch(void* const* d_in, const int* in_sizes, int n_in,
                              void* d_out, int out_size)
{
    const float* x    = (const float*)d_in[0];
    const float* W    = (const float*)d_in[1];
    const float* bias = (const float*)d_in[2];
    const float* h0   = (const float*)d_in[3];
    const float* c0   = (const float*)d_in[4];
    float* out = (float*)d_out;

    cvt_split<<<2048, 256>>>(x, W);

    size_t gemm_smem = 128 * CSTR * sizeof(float);
    cudaFuncSetAttribute(xg_gemm_tc, cudaFuncAttributeMaxDynamicSharedMemorySize,
                         (int)gemm_smem);
    dim3 grid(G_ / 128, BT_ / 128);
    xg_gemm_tc<<<grid, 256, gemm_smem>>>(bias);

    cudaFuncSetAttribute(lstm_rec, cudaFuncAttributeMaxDynamicSharedMemorySize,
                         REC_SMEM);
    lstm_rec<<<NCTA_REC, 256, REC_SMEM>>>(W, h0, c0, out);
}

// round 17
// speedup vs baseline: 1.3297x; 1.0530x over previous
#include <cuda_runtime.h>
#include <cuda_bf16.h>
#include <cuda_pipeline.h>
#include <mma.h>
#include <math.h>

#define B_  32
#define T_  2048
#define D_  512
#define H_  512
#define G_  2048
#define BT_ 65536
#define NCTA_REC 128

using namespace nvcuda;

__device__ float g_xg[65536ULL * 2048ULL];
__device__ float g_h[2][B_ * H_];
__device__ unsigned g_flags[NCTA_REC];
__device__ unsigned g_go;

__device__ __nv_bfloat16 g_xhi[65536ULL * 512ULL];
__device__ __nv_bfloat16 g_xlo[65536ULL * 512ULL];
__device__ __nv_bfloat16 g_whi[512 * 2048];
__device__ __nv_bfloat16 g_wlo[512 * 2048];

__device__ __forceinline__ unsigned ld_acq_u32(const unsigned* p)
{
    unsigned v;
    asm volatile("ld.acquire.gpu.global.u32 %0, [%1];" : "=r"(v) : "l"(p));
    return v;
}

__device__ __forceinline__ void st_rel_u32(unsigned* p, unsigned v)
{
    asm volatile("st.release.gpu.global.u32 [%0], %1;" :: "l"(p), "r"(v));
}

// ---------------------------------------------------------------------------
// Kernel A0: split x and Wx into bf16 hi/lo
// ---------------------------------------------------------------------------
__global__ __launch_bounds__(256) void cvt_split(const float* __restrict__ x,
                                                 const float* __restrict__ W)
{
    const size_t stride = (size_t)gridDim.x * blockDim.x;
    const size_t i0 = (size_t)blockIdx.x * blockDim.x + threadIdx.x;
    for (size_t i = i0; i < 65536ULL * 512ULL; i += stride) {
        float v = x[i];
        __nv_bfloat16 hv = __float2bfloat16(v);
        g_xhi[i] = hv;
        g_xlo[i] = __float2bfloat16(v - __bfloat162float(hv));
    }
    for (size_t i = i0; i < (size_t)(512 * 2048); i += stride) {
        float v = W[i];
        __nv_bfloat16 hv = __float2bfloat16(v);
        g_whi[i] = hv;
        g_wlo[i] = __float2bfloat16(v - __bfloat162float(hv));
    }
}

// ---------------------------------------------------------------------------
// Kernel A: xg = x @ Wx + b via bf16 hi/lo WMMA GEMM.
// NEW: 3-stage cp.async pipeline, ONE __syncthreads per mainloop iteration.
// 128x128 tile, BK=16, 8 warps = 2(m) x 4(n), warp tile 64x32.
// ---------------------------------------------------------------------------
#define ASTR 24
#define BSTR 136
#define CSTR 132
#define STG_A 6144
#define STG_B 4352
#define STG_BYTES (2 * STG_A + 2 * STG_B)

typedef wmma::fragment<wmma::matrix_a, 16, 16, 16, __nv_bfloat16, wmma::row_major> AFrag;
typedef wmma::fragment<wmma::matrix_b, 16, 16, 16, __nv_bfloat16, wmma::row_major> BFrag;
typedef wmma::fragment<wmma::accumulator, 16, 16, 16, float> CFrag;

__global__ __launch_bounds__(256) void xg_gemm_tc(const float* __restrict__ bias)
{
    extern __shared__ char smx[];
    float* stage = (float*)smx;

    const int tid = threadIdx.x;
    const int wid = tid >> 5;
    const int wm  = wid & 1;
    const int wn  = wid >> 1;
    const int rowBase = blockIdx.y * 128;
    const int colBase = blockIdx.x * 128;

    CFrag c[4][2];
#pragma unroll
    for (int mt = 0; mt < 4; mt++) {
#pragma unroll
        for (int nt = 0; nt < 2; nt++) {
            wmma::fill_fragment(c[mt][nt], 0.f);
        }
    }

    const int ar = tid >> 1;
    const int ac = (tid & 1) * 8;
    const int br = tid >> 4;
    const int bc = (tid & 15) * 8;
    const __nv_bfloat16* xh = g_xhi + (size_t)(rowBase + ar) * 512 + ac;
    const __nv_bfloat16* xl = g_xlo + (size_t)(rowBase + ar) * 512 + ac;
    const __nv_bfloat16* wh = g_whi + (size_t)br * 2048 + colBase + bc;
    const __nv_bfloat16* wl = g_wlo + (size_t)br * 2048 + colBase + bc;
    const int adst = ar * ASTR + ac;
    const int bdst = br * BSTR + bc;

    // Per-stage SMEM pointers
    auto stageAh = [&](int s) { return (__nv_bfloat16*)(smx + s * STG_BYTES); };
    auto stageAl = [&](int s) { return (__nv_bfloat16*)(smx + s * STG_BYTES + STG_A); };
    auto stageBh = [&](int s) { return (__nv_bfloat16*)(smx + s * STG_BYTES + 2 * STG_A); };
    auto stageBl = [&](int s) { return (__nv_bfloat16*)(smx + s * STG_BYTES + 2 * STG_A + STG_B); };

    auto issueStage = [&](int kt) {
        const int s = kt % 3;
        const int k0 = kt * 16;
        __pipeline_memcpy_async(stageAh(s) + adst, xh + k0, 16);
        __pipeline_memcpy_async(stageAl(s) + adst, xl + k0, 16);
        __pipeline_memcpy_async(stageBh(s) + bdst, wh + (size_t)k0 * 2048, 16);
        __pipeline_memcpy_async(stageBl(s) + bdst, wl + (size_t)k0 * 2048, 16);
        __pipeline_commit();
    };

    // Prologue: stages 0 and 1 in flight
    issueStage(0);
    issueStage(1);

    for (int i = 0; i < 32; i++) {
        if (i < 31) {
            __pipeline_wait_prior(1);
        } else {
            __pipeline_wait_prior(0);
        }
        __syncthreads();           // stage i ready + visible; iter i-1 consumed

        if (i + 2 < 32) {
            issueStage(i + 2);     // overwrites slot consumed at iter i-1
        }

        const int s = i % 3;
        AFrag ah[4];
        AFrag al[4];
#pragma unroll
        for (int mt = 0; mt < 4; mt++) {
            wmma::load_matrix_sync(ah[mt], stageAh(s) + (wm * 64 + mt * 16) * ASTR, ASTR);
            wmma::load_matrix_sync(al[mt], stageAl(s) + (wm * 64 + mt * 16) * ASTR, ASTR);
        }
#pragma unroll
        for (int nt = 0; nt < 2; nt++) {
            BFrag bh;
            BFrag bl;
            wmma::load_matrix_sync(bh, stageBh(s) + wn * 32 + nt * 16, BSTR);
            wmma::load_matrix_sync(bl, stageBl(s) + wn * 32 + nt * 16, BSTR);
#pragma unroll
            for (int mt = 0; mt < 4; mt++) {
                wmma::mma_sync(c[mt][nt], ah[mt], bh, c[mt][nt]);
                wmma::mma_sync(c[mt][nt], ah[mt], bl, c[mt][nt]);
                wmma::mma_sync(c[mt][nt], al[mt], bh, c[mt][nt]);
            }
        }
    }
    __syncthreads();   // all compute done before stage buffer is overwritten

#pragma unroll
    for (int mt = 0; mt < 4; mt++) {
#pragma unroll
        for (int nt = 0; nt < 2; nt++) {
            float* sp = stage + (wm * 64 + mt * 16) * CSTR + wn * 32 + nt * 16;
            wmma::store_matrix_sync(sp, c[mt][nt], CSTR, wmma::mem_row_major);
        }
    }
    __syncthreads();

    for (int idx = tid; idx < 128 * 32; idx += 256) {
        int row = idx >> 5;
        int c4  = (idx & 31) * 4;
        int r = rowBase + row;
        int t = r & (T_ - 1);
        int bb = r >> 11;
        float4 v = *(const float4*)(stage + row * CSTR + c4);
        const float* bp = bias + colBase + c4;
        v.x += bp[0];
        v.y += bp[1];
        v.z += bp[2];
        v.w += bp[3];
        *(float4*)(g_xg + ((size_t)t * B_ + bb) * G_ + colBase + c4) = v;
    }
}

// ---------------------------------------------------------------------------
// Kernel B: persistent recurrence with WMMA dot phase (round-16 winner).
// ---------------------------------------------------------------------------
#define HS_STRIDE 528
#define WH_STRIDE 24
#define PART_W    672
#define PART_MT   320
#define PART_LDM  20
#define OFF_HSLO  33792
#define OFF_WHI   67584
#define OFF_WLO   92160
#define OFF_PART  116736
#define OFF_CS    138240
#define REC_SMEM  138752

__global__ __launch_bounds__(256) void lstm_rec(const float* __restrict__ W,
                                                const float* __restrict__ h0,
                                                const float* __restrict__ c0,
                                                float* __restrict__ out)
{
    extern __shared__ char smr[];
    __nv_bfloat16* hsHi = (__nv_bfloat16*)(smr);
    __nv_bfloat16* hsLo = (__nv_bfloat16*)(smr + OFF_HSLO);
    __nv_bfloat16* wHi  = (__nv_bfloat16*)(smr + OFF_WHI);
    __nv_bfloat16* wLo  = (__nv_bfloat16*)(smr + OFF_WLO);
    float* part = (float*)(smr + OFF_PART);
    float* cs   = (float*)(smr + OFF_CS);

    const int tid = threadIdx.x;
    const int wid = tid >> 5;
    const int j   = blockIdx.x;
    const int jb  = j * 4;

    for (int e = tid; e < 8192; e += 256) {
        int k = e >> 4;
        int c = e & 15;
        int gcol = (c >> 2) * 512 + jb + (c & 3);
        float v = W[(size_t)(512 + k) * 2048 + gcol];
        __nv_bfloat16 hv = __float2bfloat16(v);
        wHi[k * WH_STRIDE + c] = hv;
        wLo[k * WH_STRIDE + c] = __float2bfloat16(v - __bfloat162float(hv));
    }
    if (tid < 128) {
        int bb = tid >> 2;
        int hc = tid & 3;
        cs[hc * 32 + bb] = c0[bb * 512 + jb + hc];
    }
    __shared__ unsigned s_fb;
    __shared__ unsigned s_gb;
    if (tid == 0) {
        s_fb = *(volatile unsigned*)&g_flags[j];
        s_gb = *(volatile unsigned*)&g_go;
    }
    __syncthreads();
    const unsigned fbase = s_fb;
    const unsigned gbase = s_gb;

    const int cb  = tid >> 2;
    const int hcl = tid & 3;

    for (int t = 0; t < T_; t++) {
        float gx[4];
        gx[0] = 0.f;
        gx[1] = 0.f;
        gx[2] = 0.f;
        gx[3] = 0.f;
        if (tid < 128) {
            const float* xp = g_xg + ((size_t)t * B_ + cb) * G_ + jb + hcl;
#pragma unroll
            for (int q = 0; q < 4; q++) {
                gx[q] = xp[q * 512];
            }
        }

        const float* hsrc = (t == 0) ? h0 : g_h[t & 1];
        for (int idx = tid; idx < 4096; idx += 256) {
            int row = idx >> 7;
            int c4  = (idx & 127) * 4;
            float4 v = *(const float4*)(hsrc + row * 512 + c4);
            __nv_bfloat16* ph = hsHi + row * HS_STRIDE + c4;
            __nv_bfloat16* pl = hsLo + row * HS_STRIDE + c4;
            __nv_bfloat16 h0b = __float2bfloat16(v.x);
            __nv_bfloat16 h1b = __float2bfloat16(v.y);
            __nv_bfloat16 h2b = __float2bfloat16(v.z);
            __nv_bfloat16 h3b = __float2bfloat16(v.w);
            ph[0] = h0b;
            ph[1] = h1b;
            ph[2] = h2b;
            ph[3] = h3b;
            pl[0] = __float2bfloat16(v.x - __bfloat162float(h0b));
            pl[1] = __float2bfloat16(v.y - __bfloat162float(h1b));
            pl[2] = __float2bfloat16(v.z - __bfloat162float(h2b));
            pl[3] = __float2bfloat16(v.w - __bfloat162float(h3b));
        }
        __syncthreads();

        {
            CFrag cf[2];
            wmma::fill_fragment(cf[0], 0.f);
            wmma::fill_fragment(cf[1], 0.f);
#pragma unroll
            for (int i = 0; i < 4; i++) {
                int k = wid * 64 + i * 16;
                BFrag bh;
                BFrag bl;
                wmma::load_matrix_sync(bh, wHi + k * WH_STRIDE, WH_STRIDE);
                wmma::load_matrix_sync(bl, wLo + k * WH_STRIDE, WH_STRIDE);
#pragma unroll
                for (int mt = 0; mt < 2; mt++) {
                    AFrag ahh;
                    AFrag alo;
                    wmma::load_matrix_sync(ahh, hsHi + mt * 16 * HS_STRIDE + k, HS_STRIDE);
                    wmma::load_matrix_sync(alo, hsLo + mt * 16 * HS_STRIDE + k, HS_STRIDE);
                    wmma::mma_sync(cf[mt], ahh, bh, cf[mt]);
                    wmma::mma_sync(cf[mt], ahh, bl, cf[mt]);
                    wmma::mma_sync(cf[mt], alo, bh, cf[mt]);
                }
            }
#pragma unroll
            for (int mt = 0; mt < 2; mt++) {
                wmma::store_matrix_sync(part + wid * PART_W + mt * PART_MT,
                                        cf[mt], PART_LDM, wmma::mem_row_major);
            }
        }
        __syncthreads();

        if (tid < 128) {
            float s0 = gx[0];
            float s1 = gx[1];
            float s2 = gx[2];
            float s3 = gx[3];
            const float* pb = part + (cb >> 4) * PART_MT + (cb & 15) * PART_LDM + hcl;
#pragma unroll
            for (int q = 0; q < 8; q++) {
                const float* pw = pb + q * PART_W;
                s0 += pw[0];
                s1 += pw[4];
                s2 += pw[8];
                s3 += pw[12];
            }
            float iv = 1.f / (1.f + expf(-s0));
            float fv = 1.f / (1.f + expf(-s1));
            float gv = tanhf(s2);
            float ov = 1.f / (1.f + expf(-s3));
            float cc = fv * cs[hcl * 32 + cb] + iv * gv;
            cs[hcl * 32 + cb] = cc;
            float hh = ov * tanhf(cc);
            g_h[(t + 1) & 1][cb * 512 + jb + hcl] = hh;
            out[((size_t)cb * T_ + t) * H_ + jb + hcl] = hh;
            if (t == T_ - 1) {
                out[(size_t)BT_ * H_ + cb * 512 + jb + hcl] = hh;
                out[(size_t)BT_ * H_ + B_ * H_ + cb * 512 + jb + hcl] = cc;
            }
        }
        __syncthreads();

        if (t < T_ - 1) {
            const unsigned step = (unsigned)t + 1u;
            if (tid == 0) {
                st_rel_u32(&g_flags[j], fbase + step);
            }
            if (j == 0) {
                if (tid < NCTA_REC) {
                    while ((int)(ld_acq_u32(&g_flags[tid]) - (fbase + step)) < 0) { }
                }
                __syncthreads();
                if (tid == 0) {
                    st_rel_u32(&g_go, gbase + step);
                }
            } else {
                if (tid == 0) {
                    while ((int)(ld_acq_u32(&g_go) - (gbase + step)) < 0) { }
                }
                __syncthreads();
            }
        }
    }
}

// ---------------------------------------------------------------------------
// Launcher
// ---------------------------------------------------------------------------
extern "C" void kernel_launch(void* const* d_in, const int* in_sizes, int n_in,
                              void* d_out, int out_size)
{
    const float* x    = (const float*)d_in[0];
    const float* W    = (const float*)d_in[1];
    const float* bias = (const float*)d_in[2];
    const float* h0   = (const float*)d_in[3];
    const float* c0   = (const float*)d_in[4];
    float* out = (float*)d_out;

    cvt_split<<<2048, 256>>>(x, W);

    size_t gemm_smem = 128 * CSTR * sizeof(float);   // 67.6 KB >= 3*STG_BYTES
    cudaFuncSetAttribute(xg_gemm_tc, cudaFuncAttributeMaxDynamicSharedMemorySize,
                         (int)gemm_smem);
    dim3 grid(G_ / 128, BT_ / 128);
    xg_gemm_tc<<<grid, 256, gemm_smem>>>(bias);

    cudaFuncSetAttribute(lstm_rec, cudaFuncAttributeMaxDynamicSharedMemorySize,
                         REC_SMEM);
    lstm_rec<<<NCTA_REC, 256, REC_SMEM>>>(W, h0, c0, out);
}